// round 11
// baseline (speedup 1.0000x reference)
#include <cuda_runtime.h>
#include <cuda_fp16.h>

#define IMG_H 256
#define IMG_W 256
#define HW    (IMG_H * IMG_W)
#define HW4   (HW / 4)

// per-block partial sums (plain stores -> no zeroing kernels needed)
__device__ float g_part_ssim[6144 * 4];    // [ssim, abs, tvh, tvv] per ssim block
__device__ float g_part_cos[512 * 2];      // [cos, mask] per cos block
__device__ int   g_part_hist[512 * 192];   // per cos block: 3ch x 64 bins

__constant__ float c_wg[11] = {
    0.0010283748f, 0.0075987582f, 0.0360007696f, 0.1093606895f, 0.2130055325f,
    0.2660117251f, 0.2130055325f, 0.1093606895f, 0.0360007696f, 0.0075987582f,
    0.0010283748f};

__device__ __forceinline__ float wsum(float v) {
#pragma unroll
    for (int o = 16; o; o >>= 1) v += __shfl_xor_sync(0xffffffffu, v, o);
    return v;
}
__device__ __forceinline__ double dsum(double v) {
#pragma unroll
    for (int o = 16; o; o >>= 1) v += __shfl_xor_sync(0xffffffffu, v, o);
    return v;
}

// ---------------------------------------------------------------------------
// SSIM tile path constants (half2, 2-field conv, 9-tap truncated gaussian)
// ---------------------------------------------------------------------------
#define TW  64
#define TH  32
#define RAD 5
#define IW  74
#define SDW 75
#define VBW 76

#define VBM_OFF   9904                         // sdc = 33*75*4 = 9900, align 16
#define VBQ_OFF   (VBM_OFF + TH * VBW * 4)     // 19632
#define SSIM_SMEM (VBQ_OFF + TH * VBW * 4)     // 29360

template <int NOUT, int O0, int OWNLO, int OWNHI>
__device__ __forceinline__ void pass1s(int c, int x0, int y0,
                                       const float* __restrict__ di,
                                       const float* __restrict__ ci,
                                       const float* __restrict__ mi,
                                       const __half2* __restrict__ w2h,
                                       __half2 (*sdc)[SDW],
                                       __half2 (*vbm)[VBW],
                                       __half2 (*vbq)[VBW]) {
    __half2 accM[NOUT], accQ[NOUT];
    __half2 z = __float2half2_rn(0.f);
#pragma unroll
    for (int o = 0; o < NOUT; o++) { accM[o] = z; accQ[o] = z; }

    int gx = x0 + c - RAD;
    bool xin = (unsigned)gx < IMG_W;

#pragma unroll
    for (int t = 0; t < NOUT + 8; t++) {
        int r  = O0 + 1 + t;
        int gy = y0 + r - RAD;
        float dv = 0.f, cv = 0.f;
        if (xin && (unsigned)gy < IMG_H) {
            int gi = gy * IMG_W + gx;
            float m = mi[gi];
            dv = di[gi] * m;
            cv = ci[gi] * m;
        }
        __half2 p = __floats2half2_rn(dv, cv);
        __half2 q = __floats2half2_rn(fmaf(dv, dv, cv * cv), dv * cv);
        if (r >= OWNLO && r <= OWNHI) sdc[r - 5][c] = p;
#pragma unroll
        for (int o = 0; o < NOUT; o++) {
            int wi = t - o;
            if (wi >= 0 && wi <= 8) {
                int k = wi < 5 ? wi : 8 - wi;
                accM[o] = __hfma2(w2h[k], p, accM[o]);
                accQ[o] = __hfma2(w2h[k], q, accQ[o]);
            }
        }
    }
#pragma unroll
    for (int o = 0; o < NOUT; o++) {
        vbm[O0 + o][c] = accM[o];
        vbq[O0 + o][c] = accQ[o];
    }
}

__device__ void ssim_block(int sbid, char* smem_raw,
                           const float* __restrict__ dz,
                           const float* __restrict__ cw,
                           const float* __restrict__ mk) {
    __half2 (*sdc)[SDW] = (__half2 (*)[SDW])smem_raw;               // rows 5..37
    __half2 (*vbm)[VBW] = (__half2 (*)[VBW])(smem_raw + VBM_OFF);
    __half2 (*vbq)[VBW] = (__half2 (*)[VBW])(smem_raw + VBQ_OFF);
    __shared__ float red[8][4];

    int tid = threadIdx.x;
    int img = sbid >> 5;           // 32 tiles per (b,c) image
    int rem = sbid & 31;
    int x0  = (rem & 3) * TW;
    int y0  = (rem >> 2) * TH;
    int b   = img / 3;
    const float* di = dz + (size_t)img * HW;
    const float* ci = cw + (size_t)img * HW;
    const float* mi = mk + (size_t)b * HW;

    __half2 w2h[5];
#pragma unroll
    for (int t = 0; t < 5; t++) w2h[t] = __float2half2_rn(c_wg[t + 1]);

    if (tid < 222) {
        int g = tid / IW, c = tid - g * IW;
        if (g == 0)      pass1s<11, 0,  5, 16>(c, x0, y0, di, ci, mi, w2h, sdc, vbm, vbq);
        else if (g == 1) pass1s<11, 11, 17, 28>(c, x0, y0, di, ci, mi, w2h, sdc, vbm, vbq);
        else             pass1s<10, 22, 29, 37>(c, x0, y0, di, ci, mi, w2h, sdc, vbm, vbq);
    }
    __syncthreads();

    int row = tid >> 3;
    int j0  = (tid & 7) * 8;

    __half2 accm[8], accq[8];
    {
        __half2 win[18];
        __half2 z = __float2half2_rn(0.f);
#pragma unroll
        for (int t = 0; t < 9; t++)
            *(uint2*)&win[2 * t] = *(const uint2*)&vbm[row][j0 + 2 * t];
#pragma unroll
        for (int jo = 0; jo < 8; jo++) {
            __half2 a = z;
#pragma unroll
            for (int t = 0; t < 9; t++)
                a = __hfma2(w2h[t < 5 ? t : 8 - t], win[jo + 1 + t], a);
            accm[jo] = a;
        }
#pragma unroll
        for (int t = 0; t < 9; t++)
            *(uint2*)&win[2 * t] = *(const uint2*)&vbq[row][j0 + 2 * t];
#pragma unroll
        for (int jo = 0; jo < 8; jo++) {
            __half2 a = z;
#pragma unroll
            for (int t = 0; t < 9; t++)
                a = __hfma2(w2h[t < 5 ? t : 8 - t], win[jo + 1 + t], a);
            accq[jo] = a;
        }
    }

    const float C1c = 1e-4f, C2c = 9e-4f;
    float a_ssim = 0.f, a_abs = 0.f, a_tvh = 0.f, a_tvv = 0.f;
#pragma unroll
    for (int jo = 0; jo < 8; jo++) {
        float2 mm = __half22float2(accm[jo]);
        float2 qq = __half22float2(accq[jo]);
        float mu1 = mm.x, mu2 = mm.y;
        float es = qq.x, ex = qq.y;
        float m1s = mu1 * mu1, m2s = mu2 * mu2, m12 = mu1 * mu2;
        float num = (2.f * m12 + C1c) * (2.f * (ex - m12) + C2c);
        float den = (m1s + m2s + C1c) * ((es - m1s - m2s) + C2c);
        a_ssim += __fdividef(num, den);

        float2 dc0 = __half22float2(sdc[row][j0 + jo + RAD]);
        a_abs += fabsf(dc0.x - dc0.y);
        if (x0 + j0 + jo + 1 < IMG_W) {
            float2 dcr = __half22float2(sdc[row][j0 + jo + RAD + 1]);
            a_tvh += fabsf(dc0.x - dcr.x);
        }
        if (y0 + row + 1 < IMG_H) {
            float2 dcd = __half22float2(sdc[row + 1][j0 + jo + RAD]);
            a_tvv += fabsf(dc0.x - dcd.x);
        }
    }

    int lane = tid & 31, wid = tid >> 5;
    a_ssim = wsum(a_ssim); a_abs = wsum(a_abs);
    a_tvh  = wsum(a_tvh);  a_tvv = wsum(a_tvv);
    if (lane == 0) {
        red[wid][0] = a_ssim; red[wid][1] = a_abs;
        red[wid][2] = a_tvh;  red[wid][3] = a_tvv;
    }
    __syncthreads();
    if (tid < 4) {
        float s = 0.f;
#pragma unroll
        for (int w = 0; w < 8; w++) s += red[w][tid];
        g_part_ssim[sbid * 4 + tid] = s;
    }
}

// ---------------------------------------------------------------------------
// cosine / normal loss + mask sum + GT histogram path
// ---------------------------------------------------------------------------
__device__ __forceinline__ void cospix(float m, float a0, float a1, float a2,
                                       float g0, float g1, float g2,
                                       float& ac, float& am) {
    float q0 = a0 * m, q1 = a1 * m, q2 = a2 * m;
    float n0 = fmaf(2.f, g0 * m, -1.f) * m;
    float n1 = fmaf(2.f, g1 * m, -1.f) * m;
    float n2 = fmaf(2.f, g2 * m, -1.f) * m;
    float pp = q0 * q0 + q1 * q1 + q2 * q2;
    float nn = n0 * n0 + n1 * n1 + n2 * n2;
    float pn = q0 * n0 + q1 * n1 + q2 * n2;
    float invn = nn > 1e-16f ? rsqrtf(nn) : 1e8f;
    float t = pp > 1e-20f ? pn * rsqrtf(pp) * invn : 0.f;
    ac += 1.f - t;
    am += m;
}

__device__ __forceinline__ void hist4(int* __restrict__ h, float4 x) {
    float xs[4] = {x.x, x.y, x.z, x.w};
#pragma unroll
    for (int k = 0; k < 4; k++) {
        float v = xs[k] * 2.f - 1.f;                 // match reference rounding
        int idx = (int)floorf((v + 1.f) * 0.5f * 64.f);
        idx = min(63, max(0, idx));
        atomicAdd(&h[idx], 1);
    }
}

#define SEG (HW4 / 8)   // 2048 float4 items per cos-block segment

__device__ void cos_block(int cbid,
                          const float4* __restrict__ pr,
                          const float4* __restrict__ gt,
                          const float4* __restrict__ mk) {
    __shared__ int sh[8][3][64];
    __shared__ float red[8][2];
    int tid = threadIdx.x, wid = tid >> 5, lane = tid & 31;
    for (int i = tid; i < 8 * 3 * 64; i += 256) ((int*)sh)[i] = 0;
    __syncthreads();

    int b   = cbid >> 3;
    int seg = cbid & 7;
    size_t base0 = (size_t)b * 3 * HW4 + (size_t)seg * SEG;
    const float4* m4p = mk + (size_t)b * HW4 + (size_t)seg * SEG;

    float a_cos = 0.f, a_m = 0.f;
    for (int i = tid; i < SEG; i += 256) {
        float4 m4 = m4p[i];
        float4 p0 = pr[base0 + i], p1 = pr[base0 + i + HW4], p2 = pr[base0 + i + 2 * HW4];
        float4 g0 = gt[base0 + i], g1 = gt[base0 + i + HW4], g2 = gt[base0 + i + 2 * HW4];
        cospix(m4.x, p0.x, p1.x, p2.x, g0.x, g1.x, g2.x, a_cos, a_m);
        cospix(m4.y, p0.y, p1.y, p2.y, g0.y, g1.y, g2.y, a_cos, a_m);
        cospix(m4.z, p0.z, p1.z, p2.z, g0.z, g1.z, g2.z, a_cos, a_m);
        cospix(m4.w, p0.w, p1.w, p2.w, g0.w, g1.w, g2.w, a_cos, a_m);
        hist4(sh[wid][0], g0);
        hist4(sh[wid][1], g1);
        hist4(sh[wid][2], g2);
    }

    a_cos = wsum(a_cos); a_m = wsum(a_m);
    if (lane == 0) { red[wid][0] = a_cos; red[wid][1] = a_m; }
    __syncthreads();
    if (tid < 2) {
        float s = 0.f;
#pragma unroll
        for (int w = 0; w < 8; w++) s += red[w][tid];
        g_part_cos[cbid * 2 + tid] = s;
    }
    if (tid < 192) {
        int tot = 0;
        int ch = tid >> 6, bin = tid & 63;
#pragma unroll
        for (int w = 0; w < 8; w++) tot += sh[w][ch][bin];
        g_part_hist[cbid * 192 + tid] = tot;
    }
}

// ---------------------------------------------------------------------------
// mega kernel: cos blocks first (stream HBM), then ssim tiles (FMA-bound)
// ---------------------------------------------------------------------------
__global__ __launch_bounds__(256, 5) void k_mega(const float* __restrict__ predict,
                                                 const float* __restrict__ gtruth,
                                                 const float* __restrict__ dz,
                                                 const float* __restrict__ cw,
                                                 const float* __restrict__ mk,
                                                 int NC) {
    extern __shared__ __align__(16) char smem_raw[];
    int bid = blockIdx.x;
    if (bid < NC) {
        cos_block(bid, (const float4*)predict, (const float4*)gtruth,
                  (const float4*)mk);
    } else {
        ssim_block(bid - NC, smem_raw, dz, cw, mk);
    }
}

// ---------------------------------------------------------------------------
// final: reduce all partials (double), compose the loss
// ---------------------------------------------------------------------------
__global__ __launch_bounds__(1024) void k_final(float* __restrict__ out,
                                                const float* __restrict__ nh, int B) {
    __shared__ double sred[32][7];
    __shared__ double fin[7];
    int tid = threadIdx.x, lane = tid & 31, wid = tid >> 5;
    int NS = B * 96, NC = B * 8, NH = B * 192;

    double acc[7] = {0, 0, 0, 0, 0, 0, 0};
    const float4* ps = (const float4*)g_part_ssim;
    for (int i = tid; i < NS; i += 1024) {
        float4 v = ps[i];
        acc[0] += v.x; acc[1] += v.y; acc[2] += v.z; acc[3] += v.w;
    }
    const float2* pc = (const float2*)g_part_cos;
    for (int i = tid; i < NC; i += 1024) {
        float2 v = pc[i];
        acc[4] += v.x; acc[5] += v.y;
    }
    for (int i = tid; i < NH; i += 1024) {
        int b = i / 192, r = i - b * 192;
        int tot = 0;
#pragma unroll
        for (int s = 0; s < 8; s++) tot += g_part_hist[(b * 8 + s) * 192 + r];
        acc[6] += fabsf(nh[i] - (float)tot * (1.f / (float)HW));
    }
#pragma unroll
    for (int k = 0; k < 7; k++) acc[k] = dsum(acc[k]);
    if (lane == 0) {
#pragma unroll
        for (int k = 0; k < 7; k++) sred[wid][k] = acc[k];
    }
    __syncthreads();
    if (tid < 7) {
        double s = 0.0;
#pragma unroll
        for (int w = 0; w < 32; w++) s += sred[w][tid];
        fin[tid] = s;
    }
    __syncthreads();
    if (tid == 0) {
        double N        = (double)B * 3.0 * (double)HW;
        double L_dehaze = fin[1] / N;
        double L_ssim   = 1.0 - fin[0] / N;
        double cnt_tv   = (double)B * 3.0 * 256.0 * 255.0;
        double L_tv     = fin[2] / cnt_tv + fin[3] / cnt_tv;
        double L_hist   = fin[6] / ((double)B * 3.0 * 64.0);
        double M        = fin[5];
        double bg       = (double)B * (double)HW - M;
        double L_normal = (fin[4] - bg) / M;
        double total = 10.0 * L_dehaze + L_ssim + L_tv + L_hist + 100.0 * L_normal;
        out[0] = (float)total;
    }
}

// ---------------------------------------------------------------------------
extern "C" void kernel_launch(void* const* d_in, const int* in_sizes, int n_in,
                              void* d_out, int out_size) {
    const float* predict = (const float*)d_in[0];
    const float* gtruth  = (const float*)d_in[1];
    const float* dz      = (const float*)d_in[2];
    const float* cw      = (const float*)d_in[3];
    const float* nh      = (const float*)d_in[4];
    const float* mk      = (const float*)d_in[5];
    int B = in_sizes[0] / (3 * IMG_H * IMG_W);
    int NC = B * 8;
    int NS = B * 96;

    static bool attr_done = false;
    if (!attr_done) {
        cudaFuncSetAttribute(k_mega, cudaFuncAttributeMaxDynamicSharedMemorySize, SSIM_SMEM);
        attr_done = true;
    }

    k_mega<<<NC + NS, 256, SSIM_SMEM>>>(predict, gtruth, dz, cw, mk, NC);
    k_final<<<1, 1024>>>((float*)d_out, nh, B);
}

// round 12
// speedup vs baseline: 1.4770x; 1.4770x over previous
#include <cuda_runtime.h>
#include <cuda_fp16.h>

#define IMG_H 256
#define IMG_W 256
#define HW    (IMG_H * IMG_W)
#define HW4   (HW / 4)

// accumulators: 0 ssim_sum, 1 absdiff, 2 tv_h, 3 tv_v, 4 unused, 5 cos_sum, 6 mask_sum
__device__ double g_acc[8];
__device__ int g_hist[64 * 3 * 64];   // per (img, bin)

__constant__ float c_wg[11] = {
    0.0010283748f, 0.0075987582f, 0.0360007696f, 0.1093606895f, 0.2130055325f,
    0.2660117251f, 0.2130055325f, 0.1093606895f, 0.0360007696f, 0.0075987582f,
    0.0010283748f};

__global__ void k_zero(int nhist) {
    int i = blockIdx.x * 256 + threadIdx.x;
    if (i < nhist) g_hist[i] = 0;
    if (blockIdx.x == 0 && threadIdx.x < 8) g_acc[threadIdx.x] = 0.0;
}

__device__ __forceinline__ float wsum(float v) {
#pragma unroll
    for (int o = 16; o; o >>= 1) v += __shfl_xor_sync(0xffffffffu, v, o);
    return v;
}

// ---------------------------------------------------------------------------
// SSIM + L1 + TV fused tiled kernel (round-10 proven version)
// ---------------------------------------------------------------------------
#define TW  64
#define TH  32
#define RAD 5
#define IW  74
#define SDW 75
#define VBW 76

#define VBM_OFF   9904                         // sdc = 33*75*4 = 9900, align 16
#define VBQ_OFF   (VBM_OFF + TH * VBW * 4)     // 19632
#define SSIM_SMEM (VBQ_OFF + TH * VBW * 4)     // 29360

template <int NOUT, int O0, int OWNLO, int OWNHI>
__device__ __forceinline__ void pass1s(int c, int x0, int y0,
                                       const float* __restrict__ di,
                                       const float* __restrict__ ci,
                                       const float* __restrict__ mi,
                                       const __half2* __restrict__ w2h,
                                       __half2 (*sdc)[SDW],
                                       __half2 (*vbm)[VBW],
                                       __half2 (*vbq)[VBW]) {
    __half2 accM[NOUT], accQ[NOUT];
    __half2 z = __float2half2_rn(0.f);
#pragma unroll
    for (int o = 0; o < NOUT; o++) { accM[o] = z; accQ[o] = z; }

    int gx = x0 + c - RAD;
    bool xin = (unsigned)gx < IMG_W;

#pragma unroll
    for (int t = 0; t < NOUT + 8; t++) {
        int r  = O0 + 1 + t;
        int gy = y0 + r - RAD;
        float dv = 0.f, cv = 0.f;
        if (xin && (unsigned)gy < IMG_H) {
            int gi = gy * IMG_W + gx;
            float m = mi[gi];
            dv = di[gi] * m;
            cv = ci[gi] * m;
        }
        __half2 p = __floats2half2_rn(dv, cv);
        __half2 q = __floats2half2_rn(fmaf(dv, dv, cv * cv), dv * cv);
        if (r >= OWNLO && r <= OWNHI) sdc[r - 5][c] = p;
#pragma unroll
        for (int o = 0; o < NOUT; o++) {
            int wi = t - o;
            if (wi >= 0 && wi <= 8) {
                int k = wi < 5 ? wi : 8 - wi;
                accM[o] = __hfma2(w2h[k], p, accM[o]);
                accQ[o] = __hfma2(w2h[k], q, accQ[o]);
            }
        }
    }
#pragma unroll
    for (int o = 0; o < NOUT; o++) {
        vbm[O0 + o][c] = accM[o];
        vbq[O0 + o][c] = accQ[o];
    }
}

__global__ __launch_bounds__(256, 5) void k_ssim(const float* __restrict__ dz,
                                                 const float* __restrict__ cw,
                                                 const float* __restrict__ mk) {
    extern __shared__ __align__(16) char smem_raw[];
    __half2 (*sdc)[SDW] = (__half2 (*)[SDW])smem_raw;               // rows 5..37
    __half2 (*vbm)[VBW] = (__half2 (*)[VBW])(smem_raw + VBM_OFF);
    __half2 (*vbq)[VBW] = (__half2 (*)[VBW])(smem_raw + VBQ_OFF);
    __shared__ float red[8][4];

    int tid = threadIdx.x;
    int img = blockIdx.z;
    int b   = img / 3;
    int x0  = blockIdx.x * TW;
    int y0  = blockIdx.y * TH;
    const float* di = dz + (size_t)img * HW;
    const float* ci = cw + (size_t)img * HW;
    const float* mi = mk + (size_t)b * HW;

    __half2 w2h[5];
#pragma unroll
    for (int t = 0; t < 5; t++) w2h[t] = __float2half2_rn(c_wg[t + 1]);

    if (tid < 222) {
        int g = tid / IW, c = tid - g * IW;
        if (g == 0)      pass1s<11, 0,  5, 16>(c, x0, y0, di, ci, mi, w2h, sdc, vbm, vbq);
        else if (g == 1) pass1s<11, 11, 17, 28>(c, x0, y0, di, ci, mi, w2h, sdc, vbm, vbq);
        else             pass1s<10, 22, 29, 37>(c, x0, y0, di, ci, mi, w2h, sdc, vbm, vbq);
    }
    __syncthreads();

    int row = tid >> 3;
    int j0  = (tid & 7) * 8;

    __half2 accm[8], accq[8];
    {
        __half2 win[18];
        __half2 z = __float2half2_rn(0.f);
#pragma unroll
        for (int t = 0; t < 9; t++)
            *(uint2*)&win[2 * t] = *(const uint2*)&vbm[row][j0 + 2 * t];
#pragma unroll
        for (int jo = 0; jo < 8; jo++) {
            __half2 a = z;
#pragma unroll
            for (int t = 0; t < 9; t++)
                a = __hfma2(w2h[t < 5 ? t : 8 - t], win[jo + 1 + t], a);
            accm[jo] = a;
        }
#pragma unroll
        for (int t = 0; t < 9; t++)
            *(uint2*)&win[2 * t] = *(const uint2*)&vbq[row][j0 + 2 * t];
#pragma unroll
        for (int jo = 0; jo < 8; jo++) {
            __half2 a = z;
#pragma unroll
            for (int t = 0; t < 9; t++)
                a = __hfma2(w2h[t < 5 ? t : 8 - t], win[jo + 1 + t], a);
            accq[jo] = a;
        }
    }

    const float C1c = 1e-4f, C2c = 9e-4f;
    float a_ssim = 0.f, a_abs = 0.f, a_tvh = 0.f, a_tvv = 0.f;
#pragma unroll
    for (int jo = 0; jo < 8; jo++) {
        float2 mm = __half22float2(accm[jo]);
        float2 qq = __half22float2(accq[jo]);
        float mu1 = mm.x, mu2 = mm.y;
        float es = qq.x, ex = qq.y;
        float m1s = mu1 * mu1, m2s = mu2 * mu2, m12 = mu1 * mu2;
        float num = (2.f * m12 + C1c) * (2.f * (ex - m12) + C2c);
        float den = (m1s + m2s + C1c) * ((es - m1s - m2s) + C2c);
        a_ssim += __fdividef(num, den);

        float2 dc0 = __half22float2(sdc[row][j0 + jo + RAD]);
        a_abs += fabsf(dc0.x - dc0.y);
        if (x0 + j0 + jo + 1 < IMG_W) {
            float2 dcr = __half22float2(sdc[row][j0 + jo + RAD + 1]);
            a_tvh += fabsf(dc0.x - dcr.x);
        }
        if (y0 + row + 1 < IMG_H) {
            float2 dcd = __half22float2(sdc[row + 1][j0 + jo + RAD]);
            a_tvv += fabsf(dc0.x - dcd.x);
        }
    }

    int lane = tid & 31, wid = tid >> 5;
    a_ssim = wsum(a_ssim); a_abs = wsum(a_abs);
    a_tvh  = wsum(a_tvh);  a_tvv = wsum(a_tvv);
    if (lane == 0) {
        red[wid][0] = a_ssim; red[wid][1] = a_abs;
        red[wid][2] = a_tvh;  red[wid][3] = a_tvv;
    }
    __syncthreads();
    if (tid < 4) {
        float s = 0.f;
#pragma unroll
        for (int w = 0; w < 8; w++) s += red[w][tid];
        atomicAdd(&g_acc[tid], (double)s);
    }
}

// ---------------------------------------------------------------------------
// cosine / normal loss + mask sum + GT histogram (round-10 proven version)
// ---------------------------------------------------------------------------
__device__ __forceinline__ void cospix(float m, float a0, float a1, float a2,
                                       float g0, float g1, float g2,
                                       float& ac, float& am) {
    float q0 = a0 * m, q1 = a1 * m, q2 = a2 * m;
    float n0 = fmaf(2.f, g0 * m, -1.f) * m;
    float n1 = fmaf(2.f, g1 * m, -1.f) * m;
    float n2 = fmaf(2.f, g2 * m, -1.f) * m;
    float pp = q0 * q0 + q1 * q1 + q2 * q2;
    float nn = n0 * n0 + n1 * n1 + n2 * n2;
    float pn = q0 * n0 + q1 * n1 + q2 * n2;
    float invn = nn > 1e-16f ? rsqrtf(nn) : 1e8f;
    float t = pp > 1e-20f ? pn * rsqrtf(pp) * invn : 0.f;
    ac += 1.f - t;
    am += m;
}

__device__ __forceinline__ void hist4(int* __restrict__ h, float4 x) {
    float xs[4] = {x.x, x.y, x.z, x.w};
#pragma unroll
    for (int k = 0; k < 4; k++) {
        float v = xs[k] * 2.f - 1.f;                 // match reference rounding
        int idx = (int)floorf((v + 1.f) * 0.5f * 64.f);
        idx = min(63, max(0, idx));
        atomicAdd(&h[idx], 1);
    }
}

#define SEG (HW4 / 8)   // 2048 float4 items per CTA segment

__global__ __launch_bounds__(256) void k_cos(const float4* __restrict__ pr,
                                             const float4* __restrict__ gt,
                                             const float4* __restrict__ mk) {
    __shared__ int sh[8][3][64];
    __shared__ float red[8][2];
    int tid = threadIdx.x, wid = tid >> 5, lane = tid & 31;
    for (int i = tid; i < 8 * 3 * 64; i += 256) ((int*)sh)[i] = 0;
    __syncthreads();

    int b   = blockIdx.x >> 3;
    int seg = blockIdx.x & 7;
    size_t base0 = (size_t)b * 3 * HW4 + (size_t)seg * SEG;
    const float4* m4p = mk + (size_t)b * HW4 + (size_t)seg * SEG;

    float a_cos = 0.f, a_m = 0.f;
    for (int i = tid; i < SEG; i += 256) {
        float4 m4 = m4p[i];
        float4 p0 = pr[base0 + i], p1 = pr[base0 + i + HW4], p2 = pr[base0 + i + 2 * HW4];
        float4 g0 = gt[base0 + i], g1 = gt[base0 + i + HW4], g2 = gt[base0 + i + 2 * HW4];
        cospix(m4.x, p0.x, p1.x, p2.x, g0.x, g1.x, g2.x, a_cos, a_m);
        cospix(m4.y, p0.y, p1.y, p2.y, g0.y, g1.y, g2.y, a_cos, a_m);
        cospix(m4.z, p0.z, p1.z, p2.z, g0.z, g1.z, g2.z, a_cos, a_m);
        cospix(m4.w, p0.w, p1.w, p2.w, g0.w, g1.w, g2.w, a_cos, a_m);
        hist4(sh[wid][0], g0);
        hist4(sh[wid][1], g1);
        hist4(sh[wid][2], g2);
    }

    a_cos = wsum(a_cos); a_m = wsum(a_m);
    if (lane == 0) { red[wid][0] = a_cos; red[wid][1] = a_m; }
    __syncthreads();
    if (tid < 2) {
        float s = 0.f;
#pragma unroll
        for (int w = 0; w < 8; w++) s += red[w][tid];
        atomicAdd(&g_acc[5 + tid], (double)s);
    }
    if (tid < 192) {
        int ch = tid >> 6, bin = tid & 63;
        int tot = 0;
#pragma unroll
        for (int w = 0; w < 8; w++) tot += sh[w][ch][bin];
        atomicAdd(&g_hist[(b * 3 + ch) * 64 + bin], tot);
    }
}

// ---------------------------------------------------------------------------
// final combine (includes hist |diff| reduction)
// ---------------------------------------------------------------------------
__global__ __launch_bounds__(512) void k_final(float* __restrict__ out,
                                               const float* __restrict__ nh, int B) {
    __shared__ float red[16];
    int tid = threadIdx.x;
    int n = B * 3 * 64;
    float a = 0.f;
    for (int i = tid; i < n; i += 512)
        a += fabsf(nh[i] - (float)g_hist[i] * (1.f / (float)HW));
    int lane = tid & 31, wid = tid >> 5;
    a = wsum(a);
    if (lane == 0) red[wid] = a;
    __syncthreads();
    if (tid == 0) {
        float hsum = 0.f;
#pragma unroll
        for (int w = 0; w < 16; w++) hsum += red[w];
        double N        = (double)B * 3.0 * (double)HW;
        double L_dehaze = g_acc[1] / N;
        double L_ssim   = 1.0 - g_acc[0] / N;
        double cnt_tv   = (double)B * 3.0 * 256.0 * 255.0;
        double L_tv     = g_acc[2] / cnt_tv + g_acc[3] / cnt_tv;
        double L_hist   = (double)hsum / ((double)B * 3.0 * 64.0);
        double M        = g_acc[6];
        double bg       = (double)B * (double)HW - M;
        double L_normal = (g_acc[5] - bg) / M;
        double total = 10.0 * L_dehaze + L_ssim + L_tv + L_hist + 100.0 * L_normal;
        out[0] = (float)total;
    }
}

// ---------------------------------------------------------------------------
extern "C" void kernel_launch(void* const* d_in, const int* in_sizes, int n_in,
                              void* d_out, int out_size) {
    const float* predict = (const float*)d_in[0];
    const float* gtruth  = (const float*)d_in[1];
    const float* dz      = (const float*)d_in[2];
    const float* cw      = (const float*)d_in[3];
    const float* nh      = (const float*)d_in[4];
    const float* mk      = (const float*)d_in[5];
    int B = in_sizes[0] / (3 * IMG_H * IMG_W);
    int nhist = B * 3 * 64;

    // one-time host-side setup on the first (uncaptured) call — no allocs
    static cudaStream_t s_side = nullptr;
    static cudaEvent_t ev_fork = nullptr, ev_join = nullptr;
    static bool init_done = false;
    if (!init_done) {
        cudaFuncSetAttribute(k_ssim, cudaFuncAttributeMaxDynamicSharedMemorySize, SSIM_SMEM);
        cudaStreamCreateWithFlags(&s_side, cudaStreamNonBlocking);
        cudaEventCreateWithFlags(&ev_fork, cudaEventDisableTiming);
        cudaEventCreateWithFlags(&ev_join, cudaEventDisableTiming);
        init_done = true;
    }

    // zero accumulators + hist, then fork: cos on side stream ∥ ssim on main
    k_zero<<<(nhist + 255) / 256, 256>>>(nhist);
    cudaEventRecord(ev_fork, 0);
    cudaStreamWaitEvent(s_side, ev_fork, 0);

    k_cos<<<B * 8, 256, 0, s_side>>>((const float4*)predict, (const float4*)gtruth,
                                     (const float4*)mk);
    cudaEventRecord(ev_join, s_side);

    dim3 gssim(IMG_W / TW, IMG_H / TH, B * 3);
    k_ssim<<<gssim, 256, SSIM_SMEM>>>(dz, cw, mk);

    cudaStreamWaitEvent(0, ev_join, 0);
    k_final<<<1, 512>>>((float*)d_out, nh, B);
}

// round 13
// speedup vs baseline: 1.7256x; 1.1683x over previous
#include <cuda_runtime.h>
#include <cuda_fp16.h>

#define IMG_H 256
#define IMG_W 256
#define HW    (IMG_H * IMG_W)
#define HW4   (HW / 4)

// accumulators: 0 ssim_sum, 1 absdiff, 2 tv_h, 3 tv_v, 4 hist_absdiff, 5 cos_sum, 6 mask_sum
__device__ double g_acc[8];
__device__ unsigned g_tick;
__device__ int g_hist[64 * 3 * 64];   // per (img, bin)

// 7-tap renormalized gaussian (taps 2..8 of the 11-tap window / 0.9827457)
__constant__ float c_w7[4] = {0.03663293f, 0.11128063f, 0.21674551f, 0.27068198f};

__global__ void k_zero(int nhist) {
    int i = blockIdx.x * 256 + threadIdx.x;
    if (i < nhist) g_hist[i] = 0;
    if (blockIdx.x == 0) {
        if (threadIdx.x < 8) g_acc[threadIdx.x] = 0.0;
        if (threadIdx.x == 8) g_tick = 0u;
    }
}

__device__ __forceinline__ float wsum(float v) {
#pragma unroll
    for (int o = 16; o; o >>= 1) v += __shfl_xor_sync(0xffffffffu, v, o);
    return v;
}

// ---------------------------------------------------------------------------
// SSIM + L1 + TV fused tiled kernel: half2, 2-field conv, 7-tap renormalized
// gaussian, pass1 streams inputs from global into register accumulators.
// ---------------------------------------------------------------------------
#define TW  64
#define TH  32
#define RAD 5
#define IW  74
#define SDW 75
#define VBW 76

#define VBM_OFF   9904                         // sdc = 33*75*4 = 9900, align 16
#define VBQ_OFF   (VBM_OFF + TH * VBW * 4)     // 19632
#define SSIM_SMEM (VBQ_OFF + TH * VBW * 4)     // 29360

// pass1: 7-tap vertical conv for column c (2..71), output rows [O0, O0+NOUT).
// output row i uses tile rows i+2 .. i+8. Stores sdc rows it owns (5..37 union).
template <int NOUT, int O0, int OWNLO, int OWNHI>
__device__ __forceinline__ void pass1s(int c, int x0, int y0,
                                       const float* __restrict__ di,
                                       const float* __restrict__ ci,
                                       const float* __restrict__ mi,
                                       const __half2* __restrict__ w7h,
                                       __half2 (*sdc)[SDW],
                                       __half2 (*vbm)[VBW],
                                       __half2 (*vbq)[VBW]) {
    __half2 accM[NOUT], accQ[NOUT];
    __half2 z = __float2half2_rn(0.f);
#pragma unroll
    for (int o = 0; o < NOUT; o++) { accM[o] = z; accQ[o] = z; }

    int gx = x0 + c - RAD;
    bool xin = (unsigned)gx < IMG_W;

#pragma unroll
    for (int t = 0; t < NOUT + 6; t++) {
        int r  = O0 + 2 + t;
        int gy = y0 + r - RAD;
        float dv = 0.f, cv = 0.f;
        if (xin && (unsigned)gy < IMG_H) {
            int gi = gy * IMG_W + gx;
            float m = mi[gi];
            dv = di[gi] * m;
            cv = ci[gi] * m;
        }
        __half2 p = __floats2half2_rn(dv, cv);
        __half2 q = __floats2half2_rn(fmaf(dv, dv, cv * cv), dv * cv);
        if (r >= OWNLO && r <= OWNHI) sdc[r - 5][c] = p;
#pragma unroll
        for (int o = 0; o < NOUT; o++) {
            int wi = t - o;                  // tap index 0..6
            if (wi >= 0 && wi <= 6) {
                int k = wi < 4 ? wi : 6 - wi;
                accM[o] = __hfma2(w7h[k], p, accM[o]);
                accQ[o] = __hfma2(w7h[k], q, accQ[o]);
            }
        }
    }
#pragma unroll
    for (int o = 0; o < NOUT; o++) {
        vbm[O0 + o][c] = accM[o];
        vbq[O0 + o][c] = accQ[o];
    }
}

__global__ __launch_bounds__(256, 5) void k_ssim(const float* __restrict__ dz,
                                                 const float* __restrict__ cw,
                                                 const float* __restrict__ mk) {
    extern __shared__ __align__(16) char smem_raw[];
    __half2 (*sdc)[SDW] = (__half2 (*)[SDW])smem_raw;               // rows 5..37
    __half2 (*vbm)[VBW] = (__half2 (*)[VBW])(smem_raw + VBM_OFF);
    __half2 (*vbq)[VBW] = (__half2 (*)[VBW])(smem_raw + VBQ_OFF);
    __shared__ float red[8][4];

    int tid = threadIdx.x;
    int img = blockIdx.z;
    int b   = img / 3;
    int x0  = blockIdx.x * TW;
    int y0  = blockIdx.y * TH;
    const float* di = dz + (size_t)img * HW;
    const float* ci = cw + (size_t)img * HW;
    const float* mi = mk + (size_t)b * HW;

    __half2 w7h[4];
#pragma unroll
    for (int t = 0; t < 4; t++) w7h[t] = __float2half2_rn(c_w7[t]);

    // ---- pass1: 210 items = 70 cols (2..71) x 3 row groups ----
    if (tid < 210) {
        int g = tid / 70, c = tid - g * 70 + 2;
        if (g == 0)      pass1s<11, 0,  5, 16>(c, x0, y0, di, ci, mi, w7h, sdc, vbm, vbq);
        else if (g == 1) pass1s<11, 11, 17, 28>(c, x0, y0, di, ci, mi, w7h, sdc, vbm, vbq);
        else             pass1s<10, 22, 29, 37>(c, x0, y0, di, ci, mi, w7h, sdc, vbm, vbq);
    }
    __syncthreads();

    // ---- pass2: horizontal conv, 256 items = 32 rows x 8 col groups of 8 --
    int row = tid >> 3;
    int j0  = (tid & 7) * 8;

    __half2 accm[8], accq[8];
    {
        __half2 win[18];
        __half2 z = __float2half2_rn(0.f);
#pragma unroll
        for (int t = 0; t < 9; t++)
            *(uint2*)&win[2 * t] = *(const uint2*)&vbm[row][j0 + 2 * t];
#pragma unroll
        for (int jo = 0; jo < 8; jo++) {
            __half2 a = z;
#pragma unroll
            for (int t = 0; t < 7; t++)       // output col j0+jo uses win[jo+2..jo+8]
                a = __hfma2(w7h[t < 4 ? t : 6 - t], win[jo + 2 + t], a);
            accm[jo] = a;
        }
#pragma unroll
        for (int t = 0; t < 9; t++)
            *(uint2*)&win[2 * t] = *(const uint2*)&vbq[row][j0 + 2 * t];
#pragma unroll
        for (int jo = 0; jo < 8; jo++) {
            __half2 a = z;
#pragma unroll
            for (int t = 0; t < 7; t++)
                a = __hfma2(w7h[t < 4 ? t : 6 - t], win[jo + 2 + t], a);
            accq[jo] = a;
        }
    }

    // ---- epilogue: ssim map + L1 + TV for 8 pixels (f32) ----
    const float C1c = 1e-4f, C2c = 9e-4f;
    float a_ssim = 0.f, a_abs = 0.f, a_tvh = 0.f, a_tvv = 0.f;
#pragma unroll
    for (int jo = 0; jo < 8; jo++) {
        float2 mm = __half22float2(accm[jo]);
        float2 qq = __half22float2(accq[jo]);
        float mu1 = mm.x, mu2 = mm.y;
        float es = qq.x, ex = qq.y;
        float m1s = mu1 * mu1, m2s = mu2 * mu2, m12 = mu1 * mu2;
        float num = (2.f * m12 + C1c) * (2.f * (ex - m12) + C2c);
        float den = (m1s + m2s + C1c) * ((es - m1s - m2s) + C2c);
        a_ssim += __fdividef(num, den);

        float2 dc0 = __half22float2(sdc[row][j0 + jo + RAD]);
        a_abs += fabsf(dc0.x - dc0.y);
        if (x0 + j0 + jo + 1 < IMG_W) {
            float2 dcr = __half22float2(sdc[row][j0 + jo + RAD + 1]);
            a_tvh += fabsf(dc0.x - dcr.x);
        }
        if (y0 + row + 1 < IMG_H) {
            float2 dcd = __half22float2(sdc[row + 1][j0 + jo + RAD]);
            a_tvv += fabsf(dc0.x - dcd.x);
        }
    }

    int lane = tid & 31, wid = tid >> 5;
    a_ssim = wsum(a_ssim); a_abs = wsum(a_abs);
    a_tvh  = wsum(a_tvh);  a_tvv = wsum(a_tvv);
    if (lane == 0) {
        red[wid][0] = a_ssim; red[wid][1] = a_abs;
        red[wid][2] = a_tvh;  red[wid][3] = a_tvv;
    }
    __syncthreads();
    if (tid < 4) {
        float s = 0.f;
#pragma unroll
        for (int w = 0; w < 8; w++) s += red[w][tid];
        atomicAdd(&g_acc[tid], (double)s);
    }
}

// ---------------------------------------------------------------------------
// cosine / normal loss + mask sum + GT histogram
// ---------------------------------------------------------------------------
__device__ __forceinline__ void cospix(float m, float a0, float a1, float a2,
                                       float g0, float g1, float g2,
                                       float& ac, float& am) {
    float q0 = a0 * m, q1 = a1 * m, q2 = a2 * m;
    float n0 = fmaf(2.f, g0 * m, -1.f) * m;
    float n1 = fmaf(2.f, g1 * m, -1.f) * m;
    float n2 = fmaf(2.f, g2 * m, -1.f) * m;
    float pp = q0 * q0 + q1 * q1 + q2 * q2;
    float nn = n0 * n0 + n1 * n1 + n2 * n2;
    float pn = q0 * n0 + q1 * n1 + q2 * n2;
    float invn = nn > 1e-16f ? rsqrtf(nn) : 1e8f;
    float t = pp > 1e-20f ? pn * rsqrtf(pp) * invn : 0.f;
    ac += 1.f - t;
    am += m;
}

__device__ __forceinline__ void hist4(int* __restrict__ h, float4 x) {
    float xs[4] = {x.x, x.y, x.z, x.w};
#pragma unroll
    for (int k = 0; k < 4; k++) {
        float v = xs[k] * 2.f - 1.f;                 // match reference rounding
        int idx = (int)floorf((v + 1.f) * 0.5f * 64.f);
        idx = min(63, max(0, idx));
        atomicAdd(&h[idx], 1);
    }
}

#define SEG (HW4 / 8)   // 2048 float4 items per CTA segment

__global__ __launch_bounds__(256) void k_cos(const float4* __restrict__ pr,
                                             const float4* __restrict__ gt,
                                             const float4* __restrict__ mk) {
    __shared__ int sh[8][3][64];
    __shared__ float red[8][2];
    int tid = threadIdx.x, wid = tid >> 5, lane = tid & 31;
    for (int i = tid; i < 8 * 3 * 64; i += 256) ((int*)sh)[i] = 0;
    __syncthreads();

    int b   = blockIdx.x >> 3;
    int seg = blockIdx.x & 7;
    size_t base0 = (size_t)b * 3 * HW4 + (size_t)seg * SEG;
    const float4* m4p = mk + (size_t)b * HW4 + (size_t)seg * SEG;

    float a_cos = 0.f, a_m = 0.f;
    for (int i = tid; i < SEG; i += 256) {
        float4 m4 = m4p[i];
        float4 p0 = pr[base0 + i], p1 = pr[base0 + i + HW4], p2 = pr[base0 + i + 2 * HW4];
        float4 g0 = gt[base0 + i], g1 = gt[base0 + i + HW4], g2 = gt[base0 + i + 2 * HW4];
        cospix(m4.x, p0.x, p1.x, p2.x, g0.x, g1.x, g2.x, a_cos, a_m);
        cospix(m4.y, p0.y, p1.y, p2.y, g0.y, g1.y, g2.y, a_cos, a_m);
        cospix(m4.z, p0.z, p1.z, p2.z, g0.z, g1.z, g2.z, a_cos, a_m);
        cospix(m4.w, p0.w, p1.w, p2.w, g0.w, g1.w, g2.w, a_cos, a_m);
        hist4(sh[wid][0], g0);
        hist4(sh[wid][1], g1);
        hist4(sh[wid][2], g2);
    }

    a_cos = wsum(a_cos); a_m = wsum(a_m);
    if (lane == 0) { red[wid][0] = a_cos; red[wid][1] = a_m; }
    __syncthreads();
    if (tid < 2) {
        float s = 0.f;
#pragma unroll
        for (int w = 0; w < 8; w++) s += red[w][tid];
        atomicAdd(&g_acc[5 + tid], (double)s);
    }
    if (tid < 192) {
        int ch = tid >> 6, bin = tid & 63;
        int tot = 0;
#pragma unroll
        for (int w = 0; w < 8; w++) tot += sh[w][ch][bin];
        atomicAdd(&g_hist[(b * 3 + ch) * 64 + bin], tot);
    }
}

// ---------------------------------------------------------------------------
// final: multi-block hist |diff| reduction; last-arriving block composes
// ---------------------------------------------------------------------------
__global__ __launch_bounds__(256) void k_final(float* __restrict__ out,
                                               const float* __restrict__ nh, int B) {
    __shared__ float red[8];
    int tid = threadIdx.x;
    int n = B * 3 * 64;
    int chunk = (n + gridDim.x - 1) / gridDim.x;
    int lo = blockIdx.x * chunk;
    int hi = min(n, lo + chunk);

    float a = 0.f;
    for (int i = lo + tid; i < hi; i += 256)
        a += fabsf(nh[i] - (float)g_hist[i] * (1.f / (float)HW));
    int lane = tid & 31, wid = tid >> 5;
    a = wsum(a);
    if (lane == 0) red[wid] = a;
    __syncthreads();
    if (tid == 0) {
        float s = 0.f;
#pragma unroll
        for (int w = 0; w < 8; w++) s += red[w];
        atomicAdd(&g_acc[4], (double)s);
        __threadfence();
        unsigned t = atomicInc(&g_tick, 0xffffffffu);
        if (t == gridDim.x - 1) {
            double N        = (double)B * 3.0 * (double)HW;
            double L_dehaze = g_acc[1] / N;
            double L_ssim   = 1.0 - g_acc[0] / N;
            double cnt_tv   = (double)B * 3.0 * 256.0 * 255.0;
            double L_tv     = g_acc[2] / cnt_tv + g_acc[3] / cnt_tv;
            double L_hist   = g_acc[4] / ((double)B * 3.0 * 64.0);
            double M        = g_acc[6];
            double bg       = (double)B * (double)HW - M;
            double L_normal = (g_acc[5] - bg) / M;
            double total = 10.0 * L_dehaze + L_ssim + L_tv + L_hist + 100.0 * L_normal;
            out[0] = (float)total;
        }
    }
}

// ---------------------------------------------------------------------------
extern "C" void kernel_launch(void* const* d_in, const int* in_sizes, int n_in,
                              void* d_out, int out_size) {
    const float* predict = (const float*)d_in[0];
    const float* gtruth  = (const float*)d_in[1];
    const float* dz      = (const float*)d_in[2];
    const float* cw      = (const float*)d_in[3];
    const float* nh      = (const float*)d_in[4];
    const float* mk      = (const float*)d_in[5];
    int B = in_sizes[0] / (3 * IMG_H * IMG_W);
    int nhist = B * 3 * 64;

    // one-time host-side setup on the first (uncaptured) call — no allocs
    static cudaStream_t s_side = nullptr;
    static cudaEvent_t ev_fork = nullptr, ev_join = nullptr;
    static bool init_done = false;
    if (!init_done) {
        cudaFuncSetAttribute(k_ssim, cudaFuncAttributeMaxDynamicSharedMemorySize, SSIM_SMEM);
        cudaStreamCreateWithFlags(&s_side, cudaStreamNonBlocking);
        cudaEventCreateWithFlags(&ev_fork, cudaEventDisableTiming);
        cudaEventCreateWithFlags(&ev_join, cudaEventDisableTiming);
        init_done = true;
    }

    // zero accumulators + hist, then fork: cos on side stream ∥ ssim on main
    k_zero<<<(nhist + 255) / 256, 256>>>(nhist);
    cudaEventRecord(ev_fork, 0);
    cudaStreamWaitEvent(s_side, ev_fork, 0);

    k_cos<<<B * 8, 256, 0, s_side>>>((const float4*)predict, (const float4*)gtruth,
                                     (const float4*)mk);
    cudaEventRecord(ev_join, s_side);

    dim3 gssim(IMG_W / TW, IMG_H / TH, B * 3);
    k_ssim<<<gssim, 256, SSIM_SMEM>>>(dz, cw, mk);

    cudaStreamWaitEvent(0, ev_join, 0);
    int nfb = max(1, (nhist + 1023) / 1024);
    k_final<<<nfb, 256>>>((float*)d_out, nh, B);
}